// round 16
// baseline (speedup 1.0000x reference)
#include <cuda_runtime.h>
#include <cuda_fp16.h>
#include <math.h>
#include <stdint.h>

#define BATCH 32
#define SEQ   2048
#define EDIM  1024
#define DDIM  1024
#define ADIM  1024

// ---------------- scratch (no allocations allowed) ----------------
__device__ float g_w[BATCH * ADIM];   // decoder projection w[b,a]
__device__ float g_e[BATCH * SEQ];    // attention energies e[b,s]
__device__ float g_m[BATCH];          // softmax max
__device__ float g_l[BATCH];          // softmax denom

// fp16 scratch
__device__ __half g_enc_h[(size_t)BATCH * SEQ * EDIM];   // 128 MB
__device__ __half g_Ut_h[ADIM * EDIM];                   // U^T [a][e]

// ---------------- helpers ----------------
__device__ __forceinline__ void cp16(uint32_t dst, const void* src) {
    asm volatile("cp.async.cg.shared.global [%0], [%1], 16;"
        :: "r"(dst), "l"((unsigned long long)__cvta_generic_to_global(src))
        : "memory");
}

#define CP_COMMIT() asm volatile("cp.async.commit_group;" ::: "memory")

#define MMA16816F16(d, a, b0, b1) \
    asm volatile("mma.sync.aligned.m16n8k16.row.col.f32.f16.f16.f32 " \
        "{%0,%1,%2,%3}, {%4,%5,%6,%7}, {%8,%9}, {%0,%1,%2,%3};" \
        : "+f"((d)[0]), "+f"((d)[1]), "+f"((d)[2]), "+f"((d)[3]) \
        : "r"((a)[0]), "r"((a)[1]), "r"((a)[2]), "r"((a)[3]), \
          "r"(b0), "r"(b1))

#define LDSM4(r0, r1, r2, r3, addr) \
    asm volatile("ldmatrix.sync.aligned.m8n8.x4.shared.b16 {%0,%1,%2,%3}, [%4];" \
        : "=r"(r0), "=r"(r1), "=r"(r2), "=r"(r3) : "r"(addr))

__device__ __forceinline__ float tanh_fast(float x) {
    float ax = fabsf(x);
    float t = __expf(-2.f * ax);
    float r = __fdividef(1.f - t, 1.f + t);
    return copysignf(r, x);
}

// ---------------------------------------------------------------------------
// convert enc to fp16. 4 floats per thread. grid 65536 x 256
// ---------------------------------------------------------------------------
__global__ void conv_enc_kernel(const float* __restrict__ src) {
    size_t i = ((size_t)blockIdx.x * 256 + threadIdx.x) * 4;
    float4 v = *(const float4*)(src + i);
    __half2* hp = (__half2*)(g_enc_h + i);
    hp[0] = __halves2half2(__float2half_rn(v.x), __float2half_rn(v.y));
    hp[1] = __halves2half2(__float2half_rn(v.z), __float2half_rn(v.w));
}

// ---------------------------------------------------------------------------
// transpose U [e][a] -> Ut [a][e] in fp16. grid (32,32), block (32,8)
// ---------------------------------------------------------------------------
__global__ void transpose_U(const float* __restrict__ U) {
    __shared__ float t[32][33];
    const int a0 = blockIdx.x * 32;
    const int e0 = blockIdx.y * 32;
    const int tx = threadIdx.x;
    const int ty = threadIdx.y;
    #pragma unroll
    for (int i = 0; i < 4; i++)
        t[ty + i * 8][tx] = U[(size_t)(e0 + ty + i * 8) * ADIM + a0 + tx];
    __syncthreads();
    #pragma unroll
    for (int i = 0; i < 4; i++) {
        size_t o = (size_t)(a0 + ty + i * 8) * EDIM + e0 + tx;
        g_Ut_h[o] = __float2half_rn(t[tx][ty + i * 8]);
    }
}

// ---------------------------------------------------------------------------
// w[b,a] = sum_d dec[b,d]*W[d,a]; zero g_e and context region
// ---------------------------------------------------------------------------
__global__ void prep_kernel(const float* __restrict__ dec,
                            const float* __restrict__ W,
                            float* __restrict__ out) {
    const int b  = blockIdx.x;
    const int ac = blockIdx.y;
    const int tid = threadIdx.x;
    const int a  = ac * 256 + tid;

    __shared__ float dsh[DDIM];
    for (int i = tid; i < DDIM; i += 256) dsh[i] = dec[b * DDIM + i];
    __syncthreads();

    float acc = 0.f;
    #pragma unroll 8
    for (int d = 0; d < DDIM; d++)
        acc += dsh[d] * W[(size_t)d * ADIM + a];
    g_w[b * ADIM + a] = acc;

    const int gt = (b * 4 + ac) * 256 + tid;
    g_e[gt] = 0.f;
    g_e[gt + 32768] = 0.f;
    out[BATCH * DDIM + gt] = 0.f;
}

// ---------------------------------------------------------------------------
// Energy GEMM: single-pass fp16 mma.sync + ldmatrix fragment feed.
// CTA 128x128, K-stage 32, triple-buffered cp.async. 256 threads (8 warps).
// Warp grid 4(M)x2(N): warp tile 32x64. grid (16, 8, 32).
// ---------------------------------------------------------------------------
#define KC 32                       // k per stage (fp16 elems)
#define PITCH 40                    // padded row pitch in fp16 (80 bytes)
#define MAT_BYTES (128 * PITCH * 2) // 10240
#define OFF_A 0
#define OFF_B (MAT_BYTES)
#define STAGE_BYTES (2 * MAT_BYTES) // 20480
#define NSTAGES (EDIM / KC)         // 32

__device__ __forceinline__ void load_stage(
    uint32_t sb,
    const __half* __restrict__ A, const __half* __restrict__ B,
    int k0, int tid)
{
    // 128 rows x 4 x 16B chunks per matrix; 2 chunks/thread each
    #pragma unroll
    for (int it = 0; it < 2; it++) {
        int i = tid + it * 256;         // 0..511
        int row = i >> 2, c = i & 3;
        uint32_t dst = (uint32_t)(row * (PITCH * 2) + c * 16);
        size_t gofs = (size_t)row * EDIM + k0 + c * 8;
        cp16(sb + OFF_A + dst, A + gofs);
        cp16(sb + OFF_B + dst, B + gofs);
    }
    CP_COMMIT();
}

__global__ __launch_bounds__(256, 1)
void energy_mma_kernel(const float* __restrict__ v) {
    const int b  = blockIdx.z;
    const int s0 = blockIdx.x * 128;
    const int a0 = blockIdx.y * 128;
    const int tid  = threadIdx.x;
    const int wid  = tid >> 5, lane = tid & 31;
    const int g    = lane >> 2, tig = lane & 3;
    const int mw   = wid >> 1, nw  = wid & 1;

    extern __shared__ char sm[];
    __shared__ float vsh[128], wsh[128];

    uint32_t smb = (uint32_t)__cvta_generic_to_shared(sm);

    if (tid < 128) {
        vsh[tid] = v[a0 + tid];
        wsh[tid] = g_w[b * ADIM + a0 + tid];
    }

    const __half* A = g_enc_h + ((size_t)b * SEQ + s0) * EDIM;
    const __half* B = g_Ut_h + (size_t)a0 * EDIM;

    // per-lane ldmatrix base offsets (within a stage), k16 added at use
    // A tile i: rows mw*32 + i*16 + (lane&15), col halves by lane>>4
    uint32_t aOff[2];
    #pragma unroll
    for (int i = 0; i < 2; i++) {
        int row = mw * 32 + i * 16 + (lane & 15);
        int col = (lane >> 4) * 8;
        aOff[i] = OFF_A + (uint32_t)(row * PITCH + col) * 2;
    }
    // B pair p: rows nw*64 + p*16 + (lane>>4)*8 + (lane&7), col by (lane>>3)&1
    uint32_t bOff[4];
    #pragma unroll
    for (int p = 0; p < 4; p++) {
        int row = nw * 64 + p * 16 + ((lane >> 4) << 3) + (lane & 7);
        int col = ((lane >> 3) & 1) * 8;
        bOff[p] = OFF_B + (uint32_t)(row * PITCH + col) * 2;
    }

    float acc[2][8][4];
    #pragma unroll
    for (int i = 0; i < 2; i++)
        #pragma unroll
        for (int j = 0; j < 8; j++)
            #pragma unroll
            for (int c = 0; c < 4; c++) acc[i][j][c] = 0.f;

    load_stage(smb + 0 * STAGE_BYTES, A, B, 0,  tid);
    load_stage(smb + 1 * STAGE_BYTES, A, B, KC, tid);

    #pragma unroll 1
    for (int s = 0; s < NSTAGES; s++) {
        if (s == NSTAGES - 1) {
            asm volatile("cp.async.wait_group 0;" ::: "memory");
        } else {
            asm volatile("cp.async.wait_group 1;" ::: "memory");
        }
        __syncthreads();

        if (s + 2 < NSTAGES)
            load_stage(smb + (uint32_t)((s + 2) % 3) * STAGE_BYTES,
                       A, B, (s + 2) * KC, tid);

        uint32_t stg = smb + (uint32_t)(s % 3) * STAGE_BYTES;

        #pragma unroll
        for (int kk = 0; kk < 2; kk++) {
            const uint32_t kOff = (uint32_t)(kk * 16 * 2);
            // A fragments: 2 m-tiles, one ldmatrix.x4 each
            uint32_t af[2][4];
            #pragma unroll
            for (int i = 0; i < 2; i++)
                LDSM4(af[i][0], af[i][1], af[i][2], af[i][3],
                      stg + aOff[i] + kOff);
            // B fragments: 4 pairs of j-tiles, one ldmatrix.x4 each
            uint32_t bf[4][4];
            #pragma unroll
            for (int p = 0; p < 4; p++)
                LDSM4(bf[p][0], bf[p][1], bf[p][2], bf[p][3],
                      stg + bOff[p] + kOff);
            // MMAs: j = 2p -> {bf[p][0], bf[p][1]}, j = 2p+1 -> {bf[p][2], bf[p][3]}
            #pragma unroll
            for (int p = 0; p < 4; p++) {
                #pragma unroll
                for (int i = 0; i < 2; i++) {
                    MMA16816F16(acc[i][2 * p],     af[i], bf[p][0], bf[p][1]);
                    MMA16816F16(acc[i][2 * p + 1], af[i], bf[p][2], bf[p][3]);
                }
            }
        }
        __syncthreads();
    }

    // epilogue: p(row) = sum over this thread's cols of v*tanh(w+u)
    // column of acc[i][j]: nw*64 + (j>>1)*16 + (j&1)*8 + 2*tig
    #pragma unroll
    for (int i = 0; i < 2; i++) {
        float p0 = 0.f, p1 = 0.f;
        #pragma unroll
        for (int j = 0; j < 8; j++) {
            int c = nw * 64 + (j >> 1) * 16 + (j & 1) * 8 + 2 * tig;
            p0 += vsh[c]     * tanh_fast(wsh[c]     + acc[i][j][0]);
            p0 += vsh[c + 1] * tanh_fast(wsh[c + 1] + acc[i][j][1]);
            p1 += vsh[c]     * tanh_fast(wsh[c]     + acc[i][j][2]);
            p1 += vsh[c + 1] * tanh_fast(wsh[c + 1] + acc[i][j][3]);
        }
        // reduce across the 4 tig lanes (same g -> same rows)
        p0 += __shfl_xor_sync(0xffffffffu, p0, 1);
        p0 += __shfl_xor_sync(0xffffffffu, p0, 2);
        p1 += __shfl_xor_sync(0xffffffffu, p1, 1);
        p1 += __shfl_xor_sync(0xffffffffu, p1, 2);
        if (tig == 0) {
            int r = s0 + mw * 32 + i * 16 + g;
            atomicAdd(&g_e[b * SEQ + r], p0);
            atomicAdd(&g_e[b * SEQ + r + 8], p1);
        }
    }
}

// ---------------------------------------------------------------------------
// softmax stats
// ---------------------------------------------------------------------------
__global__ void stats_kernel() {
    const int b = blockIdx.x;
    const int tid = threadIdx.x;
    __shared__ float red[256];

    float vals[8];
    float m = -INFINITY;
    #pragma unroll
    for (int i = 0; i < 8; i++) {
        vals[i] = g_e[b * SEQ + tid + i * 256];
        m = fmaxf(m, vals[i]);
    }
    red[tid] = m;
    __syncthreads();
    for (int off = 128; off > 0; off >>= 1) {
        if (tid < off) red[tid] = fmaxf(red[tid], red[tid + off]);
        __syncthreads();
    }
    m = red[0];
    __syncthreads();

    float s = 0.f;
    #pragma unroll
    for (int i = 0; i < 8; i++) s += __expf(vals[i] - m);
    red[tid] = s;
    __syncthreads();
    for (int off = 128; off > 0; off >>= 1) {
        if (tid < off) red[tid] += red[tid + off];
        __syncthreads();
    }
    if (tid == 0) { g_m[b] = m; g_l[b] = red[0]; }
}

// ---------------------------------------------------------------------------
// context[b,e] = sum_s softmax(e)[b,s] * enc[b,s,e]
// ---------------------------------------------------------------------------
__global__ void context_kernel(const float* __restrict__ enc,
                               float* __restrict__ out) {
    const int sc = blockIdx.x;
    const int b  = blockIdx.y;
    const int tid = threadIdx.x;

    __shared__ float p[128];
    const float m = g_m[b];
    const float inv_l = 1.f / g_l[b];
    if (tid < 128)
        p[tid] = __expf(g_e[b * SEQ + sc * 128 + tid] - m) * inv_l;
    __syncthreads();

    const float* base = enc + (size_t)b * SEQ * EDIM + (size_t)sc * 128 * EDIM + tid * 4;
    float4 acc = make_float4(0.f, 0.f, 0.f, 0.f);
    #pragma unroll 4
    for (int s = 0; s < 128; s++) {
        float ps = p[s];
        float4 x = *(const float4*)(base + (size_t)s * EDIM);
        acc.x += ps * x.x;
        acc.y += ps * x.y;
        acc.z += ps * x.z;
        acc.w += ps * x.w;
    }
    float* ctx = out + BATCH * DDIM + b * EDIM + tid * 4;
    atomicAdd(ctx + 0, acc.x);
    atomicAdd(ctx + 1, acc.y);
    atomicAdd(ctx + 2, acc.z);
    atomicAdd(ctx + 3, acc.w);
}

// ---------------------------------------------------------------------------
// output[b,o] = tanh( sum_d cat[b,d] * ffn[d,o] ), cat=[dec,ctx]
// ---------------------------------------------------------------------------
__global__ void output_kernel(const float* __restrict__ dec,
                              const float* __restrict__ ffn,
                              float* __restrict__ out) {
    const int b  = blockIdx.x;
    const int oc = blockIdx.y;
    const int tid = threadIdx.x;
    const int o  = oc * 256 + tid;

    __shared__ float cat[EDIM + DDIM];
    for (int i = tid; i < DDIM; i += 256) cat[i] = dec[b * DDIM + i];
    for (int i = tid; i < EDIM; i += 256)
        cat[DDIM + i] = out[BATCH * DDIM + b * EDIM + i];
    __syncthreads();

    float acc = 0.f;
    #pragma unroll 8
    for (int d = 0; d < EDIM + DDIM; d++)
        acc += cat[d] * ffn[(size_t)d * DDIM + o];
    out[b * DDIM + o] = tanhf(acc);
}

// ---------------------------------------------------------------------------
extern "C" void kernel_launch(void* const* d_in, const int* in_sizes, int n_in,
                              void* d_out, int out_size) {
    const float* enc = (const float*)d_in[0];   // [B,S,E]
    const float* dec = (const float*)d_in[1];   // [B,1,D]
    const float* U_a = (const float*)d_in[2];   // [E,A]
    const float* W_a = (const float*)d_in[3];   // [D,A]
    const float* v_t = (const float*)d_in[4];   // [A,1]
    const float* ffn = (const float*)d_in[5];   // [E+D, D]
    float* out = (float*)d_out;                 // [B*D output | B*E context]

    (void)in_sizes; (void)n_in; (void)out_size;

    const int dyn_smem = STAGE_BYTES * 3;       // 61440
    cudaFuncSetAttribute(energy_mma_kernel,
                         cudaFuncAttributeMaxDynamicSharedMemorySize, dyn_smem);

    conv_enc_kernel<<<65536, 256>>>(enc);
    transpose_U<<<dim3(32, 32), dim3(32, 8)>>>(U_a);
    prep_kernel<<<dim3(BATCH, 4), 256>>>(dec, W_a, out);
    energy_mma_kernel<<<dim3(SEQ / 128, ADIM / 128, BATCH), 256, dyn_smem>>>(v_t);
    stats_kernel<<<BATCH, 256>>>();
    context_kernel<<<dim3(16, BATCH), 256>>>(enc, out);
    output_kernel<<<dim3(BATCH, 4), 256>>>(dec, ffn, out);
}

// round 17
// speedup vs baseline: 1.2255x; 1.2255x over previous
#include <cuda_runtime.h>
#include <cuda_fp16.h>
#include <math.h>
#include <stdint.h>

#define BATCH 32
#define SEQ   2048
#define EDIM  1024
#define DDIM  1024
#define ADIM  1024

// ---------------- scratch (no allocations allowed) ----------------
__device__ float g_w[BATCH * ADIM];   // decoder projection w[b,a]
__device__ float g_e[BATCH * SEQ];    // attention energies e[b,s]
__device__ float g_m[BATCH];          // softmax max
__device__ float g_l[BATCH];          // softmax denom

// fp16 scratch
__device__ __half g_enc_h[(size_t)BATCH * SEQ * EDIM];   // 128 MB
__device__ __half g_Ut_h[ADIM * EDIM];                   // U^T [a][e]

// ---------------- helpers ----------------
__device__ __forceinline__ void cp16(uint32_t dst, const void* src) {
    asm volatile("cp.async.cg.shared.global [%0], [%1], 16;"
        :: "r"(dst), "l"((unsigned long long)__cvta_generic_to_global(src))
        : "memory");
}

#define CP_COMMIT() asm volatile("cp.async.commit_group;" ::: "memory")

#define MMA16816F16(d, a, b0, b1) \
    asm volatile("mma.sync.aligned.m16n8k16.row.col.f32.f16.f16.f32 " \
        "{%0,%1,%2,%3}, {%4,%5,%6,%7}, {%8,%9}, {%0,%1,%2,%3};" \
        : "+f"((d)[0]), "+f"((d)[1]), "+f"((d)[2]), "+f"((d)[3]) \
        : "r"((a)[0]), "r"((a)[1]), "r"((a)[2]), "r"((a)[3]), \
          "r"(b0), "r"(b1))

#define LDSM4(r0, r1, r2, r3, addr) \
    asm volatile("ldmatrix.sync.aligned.m8n8.x4.shared.b16 {%0,%1,%2,%3}, [%4];" \
        : "=r"(r0), "=r"(r1), "=r"(r2), "=r"(r3) : "r"(addr))

__device__ __forceinline__ float tanh_fast(float x) {
    float ax = fabsf(x);
    float t = __expf(-2.f * ax);
    float r = __fdividef(1.f - t, 1.f + t);
    return copysignf(r, x);
}

// ---------------------------------------------------------------------------
// convert enc to fp16. 4 floats per thread. grid 65536 x 256
// ---------------------------------------------------------------------------
__global__ void conv_enc_kernel(const float* __restrict__ src) {
    size_t i = ((size_t)blockIdx.x * 256 + threadIdx.x) * 4;
    float4 v = *(const float4*)(src + i);
    __half2* hp = (__half2*)(g_enc_h + i);
    hp[0] = __halves2half2(__float2half_rn(v.x), __float2half_rn(v.y));
    hp[1] = __halves2half2(__float2half_rn(v.z), __float2half_rn(v.w));
}

// ---------------------------------------------------------------------------
// transpose U [e][a] -> Ut [a][e] in fp16. grid (32,32), block (32,8)
// ---------------------------------------------------------------------------
__global__ void transpose_U(const float* __restrict__ U) {
    __shared__ float t[32][33];
    const int a0 = blockIdx.x * 32;
    const int e0 = blockIdx.y * 32;
    const int tx = threadIdx.x;
    const int ty = threadIdx.y;
    #pragma unroll
    for (int i = 0; i < 4; i++)
        t[ty + i * 8][tx] = U[(size_t)(e0 + ty + i * 8) * ADIM + a0 + tx];
    __syncthreads();
    #pragma unroll
    for (int i = 0; i < 4; i++) {
        size_t o = (size_t)(a0 + ty + i * 8) * EDIM + e0 + tx;
        g_Ut_h[o] = __float2half_rn(t[tx][ty + i * 8]);
    }
}

// ---------------------------------------------------------------------------
// w[b,a] = sum_d dec[b,d]*W[d,a]; zero g_e and context region
// ---------------------------------------------------------------------------
__global__ void prep_kernel(const float* __restrict__ dec,
                            const float* __restrict__ W,
                            float* __restrict__ out) {
    const int b  = blockIdx.x;
    const int ac = blockIdx.y;
    const int tid = threadIdx.x;
    const int a  = ac * 256 + tid;

    __shared__ float dsh[DDIM];
    for (int i = tid; i < DDIM; i += 256) dsh[i] = dec[b * DDIM + i];
    __syncthreads();

    float acc = 0.f;
    #pragma unroll 8
    for (int d = 0; d < DDIM; d++)
        acc += dsh[d] * W[(size_t)d * ADIM + a];
    g_w[b * ADIM + a] = acc;

    const int gt = (b * 4 + ac) * 256 + tid;
    g_e[gt] = 0.f;
    g_e[gt + 32768] = 0.f;
    out[BATCH * DDIM + gt] = 0.f;
}

// ---------------------------------------------------------------------------
// Energy GEMM: single-pass fp16 mma.sync + ldmatrix fragment feed.
// CTA 128x128, K-stage 32, triple-buffered cp.async. 256 threads (8 warps).
// 2 CTAs/SM for cross-CTA barrier-bubble hiding.
// Warp grid 4(M)x2(N): warp tile 32x64. grid (16, 8, 32).
// ---------------------------------------------------------------------------
#define KC 32                       // k per stage (fp16 elems)
#define PITCH 40                    // padded row pitch in fp16 (80 bytes)
#define MAT_BYTES (128 * PITCH * 2) // 10240
#define OFF_A 0
#define OFF_B (MAT_BYTES)
#define STAGE_BYTES (2 * MAT_BYTES) // 20480
#define NSTAGES (EDIM / KC)         // 32

__device__ __forceinline__ void load_stage(
    uint32_t sb,
    const __half* __restrict__ A, const __half* __restrict__ B,
    int k0, int tid)
{
    // 128 rows x 4 x 16B chunks per matrix; 2 chunks/thread each
    #pragma unroll
    for (int it = 0; it < 2; it++) {
        int i = tid + it * 256;         // 0..511
        int row = i >> 2, c = i & 3;
        uint32_t dst = (uint32_t)(row * (PITCH * 2) + c * 16);
        size_t gofs = (size_t)row * EDIM + k0 + c * 8;
        cp16(sb + OFF_A + dst, A + gofs);
        cp16(sb + OFF_B + dst, B + gofs);
    }
    CP_COMMIT();
}

__global__ __launch_bounds__(256, 2)
void energy_mma_kernel(const float* __restrict__ v) {
    const int b  = blockIdx.z;
    const int s0 = blockIdx.x * 128;
    const int a0 = blockIdx.y * 128;
    const int tid  = threadIdx.x;
    const int wid  = tid >> 5, lane = tid & 31;
    const int g    = lane >> 2, tig = lane & 3;
    const int mw   = wid >> 1, nw  = wid & 1;

    extern __shared__ char sm[];
    __shared__ float vsh[128], wsh[128];

    uint32_t smb = (uint32_t)__cvta_generic_to_shared(sm);

    if (tid < 128) {
        vsh[tid] = v[a0 + tid];
        wsh[tid] = g_w[b * ADIM + a0 + tid];
    }

    const __half* A = g_enc_h + ((size_t)b * SEQ + s0) * EDIM;
    const __half* B = g_Ut_h + (size_t)a0 * EDIM;

    // per-lane ldmatrix base offsets (within a stage), k16 added at use
    // A tile i: rows mw*32 + i*16 + (lane&15), col halves by lane>>4
    uint32_t aOff[2];
    #pragma unroll
    for (int i = 0; i < 2; i++) {
        int row = mw * 32 + i * 16 + (lane & 15);
        int col = (lane >> 4) * 8;
        aOff[i] = OFF_A + (uint32_t)(row * PITCH + col) * 2;
    }
    // B pair p: rows nw*64 + p*16 + (lane>>4)*8 + (lane&7), col by (lane>>3)&1
    uint32_t bOff[4];
    #pragma unroll
    for (int p = 0; p < 4; p++) {
        int row = nw * 64 + p * 16 + ((lane >> 4) << 3) + (lane & 7);
        int col = ((lane >> 3) & 1) * 8;
        bOff[p] = OFF_B + (uint32_t)(row * PITCH + col) * 2;
    }

    float acc[2][8][4];
    #pragma unroll
    for (int i = 0; i < 2; i++)
        #pragma unroll
        for (int j = 0; j < 8; j++)
            #pragma unroll
            for (int c = 0; c < 4; c++) acc[i][j][c] = 0.f;

    load_stage(smb + 0 * STAGE_BYTES, A, B, 0,  tid);
    load_stage(smb + 1 * STAGE_BYTES, A, B, KC, tid);

    #pragma unroll 1
    for (int s = 0; s < NSTAGES; s++) {
        if (s == NSTAGES - 1) {
            asm volatile("cp.async.wait_group 0;" ::: "memory");
        } else {
            asm volatile("cp.async.wait_group 1;" ::: "memory");
        }
        __syncthreads();

        if (s + 2 < NSTAGES)
            load_stage(smb + (uint32_t)((s + 2) % 3) * STAGE_BYTES,
                       A, B, (s + 2) * KC, tid);

        uint32_t stg = smb + (uint32_t)(s % 3) * STAGE_BYTES;

        #pragma unroll
        for (int kk = 0; kk < 2; kk++) {
            const uint32_t kOff = (uint32_t)(kk * 16 * 2);
            // A fragments: 2 m-tiles, one ldmatrix.x4 each
            uint32_t af[2][4];
            #pragma unroll
            for (int i = 0; i < 2; i++)
                LDSM4(af[i][0], af[i][1], af[i][2], af[i][3],
                      stg + aOff[i] + kOff);
            // B fragments: 4 pairs of j-tiles, one ldmatrix.x4 each
            uint32_t bf[4][4];
            #pragma unroll
            for (int p = 0; p < 4; p++)
                LDSM4(bf[p][0], bf[p][1], bf[p][2], bf[p][3],
                      stg + bOff[p] + kOff);
            // MMAs: j = 2p -> {bf[p][0], bf[p][1]}, j = 2p+1 -> {bf[p][2], bf[p][3]}
            #pragma unroll
            for (int p = 0; p < 4; p++) {
                #pragma unroll
                for (int i = 0; i < 2; i++) {
                    MMA16816F16(acc[i][2 * p],     af[i], bf[p][0], bf[p][1]);
                    MMA16816F16(acc[i][2 * p + 1], af[i], bf[p][2], bf[p][3]);
                }
            }
        }
        __syncthreads();
    }

    // epilogue: p(row) = sum over this thread's cols of v*tanh(w+u)
    // column of acc[i][j]: nw*64 + (j>>1)*16 + (j&1)*8 + 2*tig
    #pragma unroll
    for (int i = 0; i < 2; i++) {
        float p0 = 0.f, p1 = 0.f;
        #pragma unroll
        for (int j = 0; j < 8; j++) {
            int c = nw * 64 + (j >> 1) * 16 + (j & 1) * 8 + 2 * tig;
            p0 += vsh[c]     * tanh_fast(wsh[c]     + acc[i][j][0]);
            p0 += vsh[c + 1] * tanh_fast(wsh[c + 1] + acc[i][j][1]);
            p1 += vsh[c]     * tanh_fast(wsh[c]     + acc[i][j][2]);
            p1 += vsh[c + 1] * tanh_fast(wsh[c + 1] + acc[i][j][3]);
        }
        // reduce across the 4 tig lanes (same g -> same rows)
        p0 += __shfl_xor_sync(0xffffffffu, p0, 1);
        p0 += __shfl_xor_sync(0xffffffffu, p0, 2);
        p1 += __shfl_xor_sync(0xffffffffu, p1, 1);
        p1 += __shfl_xor_sync(0xffffffffu, p1, 2);
        if (tig == 0) {
            int r = s0 + mw * 32 + i * 16 + g;
            atomicAdd(&g_e[b * SEQ + r], p0);
            atomicAdd(&g_e[b * SEQ + r + 8], p1);
        }
    }
}

// ---------------------------------------------------------------------------
// softmax stats
// ---------------------------------------------------------------------------
__global__ void stats_kernel() {
    const int b = blockIdx.x;
    const int tid = threadIdx.x;
    __shared__ float red[256];

    float vals[8];
    float m = -INFINITY;
    #pragma unroll
    for (int i = 0; i < 8; i++) {
        vals[i] = g_e[b * SEQ + tid + i * 256];
        m = fmaxf(m, vals[i]);
    }
    red[tid] = m;
    __syncthreads();
    for (int off = 128; off > 0; off >>= 1) {
        if (tid < off) red[tid] = fmaxf(red[tid], red[tid + off]);
        __syncthreads();
    }
    m = red[0];
    __syncthreads();

    float s = 0.f;
    #pragma unroll
    for (int i = 0; i < 8; i++) s += __expf(vals[i] - m);
    red[tid] = s;
    __syncthreads();
    for (int off = 128; off > 0; off >>= 1) {
        if (tid < off) red[tid] += red[tid + off];
        __syncthreads();
    }
    if (tid == 0) { g_m[b] = m; g_l[b] = red[0]; }
}

// ---------------------------------------------------------------------------
// context[b,e] = sum_s softmax(e)[b,s] * enc[b,s,e]
// ---------------------------------------------------------------------------
__global__ void context_kernel(const float* __restrict__ enc,
                               float* __restrict__ out) {
    const int sc = blockIdx.x;
    const int b  = blockIdx.y;
    const int tid = threadIdx.x;

    __shared__ float p[128];
    const float m = g_m[b];
    const float inv_l = 1.f / g_l[b];
    if (tid < 128)
        p[tid] = __expf(g_e[b * SEQ + sc * 128 + tid] - m) * inv_l;
    __syncthreads();

    const float* base = enc + (size_t)b * SEQ * EDIM + (size_t)sc * 128 * EDIM + tid * 4;
    float4 acc = make_float4(0.f, 0.f, 0.f, 0.f);
    #pragma unroll 4
    for (int s = 0; s < 128; s++) {
        float ps = p[s];
        float4 x = *(const float4*)(base + (size_t)s * EDIM);
        acc.x += ps * x.x;
        acc.y += ps * x.y;
        acc.z += ps * x.z;
        acc.w += ps * x.w;
    }
    float* ctx = out + BATCH * DDIM + b * EDIM + tid * 4;
    atomicAdd(ctx + 0, acc.x);
    atomicAdd(ctx + 1, acc.y);
    atomicAdd(ctx + 2, acc.z);
    atomicAdd(ctx + 3, acc.w);
}

// ---------------------------------------------------------------------------
// output[b,o] = tanh( sum_d cat[b,d] * ffn[d,o] ), cat=[dec,ctx]
// ---------------------------------------------------------------------------
__global__ void output_kernel(const float* __restrict__ dec,
                              const float* __restrict__ ffn,
                              float* __restrict__ out) {
    const int b  = blockIdx.x;
    const int oc = blockIdx.y;
    const int tid = threadIdx.x;
    const int o  = oc * 256 + tid;

    __shared__ float cat[EDIM + DDIM];
    for (int i = tid; i < DDIM; i += 256) cat[i] = dec[b * DDIM + i];
    for (int i = tid; i < EDIM; i += 256)
        cat[DDIM + i] = out[BATCH * DDIM + b * EDIM + i];
    __syncthreads();

    float acc = 0.f;
    #pragma unroll 8
    for (int d = 0; d < EDIM + DDIM; d++)
        acc += cat[d] * ffn[(size_t)d * DDIM + o];
    out[b * DDIM + o] = tanhf(acc);
}

// ---------------------------------------------------------------------------
extern "C" void kernel_launch(void* const* d_in, const int* in_sizes, int n_in,
                              void* d_out, int out_size) {
    const float* enc = (const float*)d_in[0];   // [B,S,E]
    const float* dec = (const float*)d_in[1];   // [B,1,D]
    const float* U_a = (const float*)d_in[2];   // [E,A]
    const float* W_a = (const float*)d_in[3];   // [D,A]
    const float* v_t = (const float*)d_in[4];   // [A,1]
    const float* ffn = (const float*)d_in[5];   // [E+D, D]
    float* out = (float*)d_out;                 // [B*D output | B*E context]

    (void)in_sizes; (void)n_in; (void)out_size;

    const int dyn_smem = STAGE_BYTES * 3;       // 61440
    cudaFuncSetAttribute(energy_mma_kernel,
                         cudaFuncAttributeMaxDynamicSharedMemorySize, dyn_smem);

    conv_enc_kernel<<<65536, 256>>>(enc);
    transpose_U<<<dim3(32, 32), dim3(32, 8)>>>(U_a);
    prep_kernel<<<dim3(BATCH, 4), 256>>>(dec, W_a, out);
    energy_mma_kernel<<<dim3(SEQ / 128, ADIM / 128, BATCH), 256, dyn_smem>>>(v_t);
    stats_kernel<<<BATCH, 256>>>();
    context_kernel<<<dim3(16, BATCH), 256>>>(enc, out);
    output_kernel<<<dim3(BATCH, 4), 256>>>(dec, ffn, out);
}